// round 15
// baseline (speedup 1.0000x reference)
#include <cuda_runtime.h>
#include <cuda_fp16.h>
#include <cstdint>

#define NS_MAX 100000
#define NP_MAX 20000
#define E_MAX  500000
#define HF 128

// ======================= device scratch (no allocation allowed) ==============
__device__ __half g_song16[NS_MAX * HF];
__device__ __half g_play16[NP_MAX * HF];
__device__ __half g_p116  [NP_MAX * HF];
__device__ __half g_s116  [NS_MAX * HF];
__device__ __half g_W16[4][HF * 256];   // B[n][k], k = concat(Wl,Wr), fp16

__device__ int g_cntP[NP_MAX], g_cntS[NS_MAX];
__device__ int g_offP[NP_MAX], g_offS[NS_MAX];
__device__ int g_curP[NP_MAX], g_curS[NS_MAX];
__device__ int g_adjP[E_MAX], g_adjS[E_MAX];
__device__ int g_totP, g_totS;

// ======================= helpers =============================================
__device__ __forceinline__ uint32_t smem_u32(const void* p) {
    uint32_t a;
    asm("{ .reg .u64 t; cvta.to.shared.u64 t, %1; cvt.u32.u64 %0, t; }" : "=r"(a) : "l"(p));
    return a;
}
__device__ __forceinline__ uint32_t pack2h(float a, float b) {
    __half2 h = __floats2half2_rn(a, b);
    return *(uint32_t*)&h;
}
__device__ __forceinline__ void ldsm_x4(uint32_t* r, uint32_t addr) {
    asm volatile("ldmatrix.sync.aligned.m8n8.x4.shared.b16 {%0,%1,%2,%3}, [%4];"
                 : "=r"(r[0]), "=r"(r[1]), "=r"(r[2]), "=r"(r[3]) : "r"(addr));
}
__device__ __forceinline__ void mma_f16(float* d, const uint32_t* a, const uint32_t* b) {
    asm volatile("mma.sync.aligned.m16n8k16.row.col.f32.f16.f16.f32 "
                 "{%0,%1,%2,%3}, {%4,%5,%6,%7}, {%8,%9}, {%0,%1,%2,%3};"
                 : "+f"(d[0]), "+f"(d[1]), "+f"(d[2]), "+f"(d[3])
                 : "r"(a[0]), "r"(a[1]), "r"(a[2]), "r"(a[3]), "r"(b[0]), "r"(b[1]));
}

// ======================= graph-structure build ===============================
__global__ void zero_cnt(int* __restrict__ cntP, int nP, int* __restrict__ cntS, int nS,
                         int* __restrict__ totP, int* __restrict__ totS) {
    int i = blockIdx.x * blockDim.x + threadIdx.x;
    if (i < nP) cntP[i] = 0;
    if (i < nS) cntS[i] = 0;
    if (i == 0) { *totP = 0; *totS = 0; }
}

__global__ void count_kernel(const int* __restrict__ es, const int* __restrict__ ep,
                             int* __restrict__ cntS, int* __restrict__ cntP, int E) {
    int i = blockIdx.x * blockDim.x + threadIdx.x;
    if (i >= E) return;
    atomicAdd(&cntS[es[i]], 1);
    atomicAdd(&cntP[ep[i]], 1);
}

// parallel CSR allocation: block scan + one atomicAdd of block total.
__device__ __forceinline__ void alloc_seg(const int* __restrict__ cnt, int* __restrict__ off,
                                          int* __restrict__ cur, int n, int* __restrict__ gTot,
                                          int blk) {
    __shared__ int wsum[8];
    __shared__ int blockBase;
    const int tid = threadIdx.x, lane = tid & 31, wid = tid >> 5;
    int i = blk * 256 + tid;
    int v = (i < n) ? cnt[i] : 0;
    int x = v;
    #pragma unroll
    for (int d = 1; d < 32; d <<= 1) { int y = __shfl_up_sync(~0u, x, d); if (lane >= d) x += y; }
    if (lane == 31) wsum[wid] = x;
    __syncthreads();
    if (wid == 0) {
        int ws = (lane < 8) ? wsum[lane] : 0;
        #pragma unroll
        for (int d = 1; d < 8; d <<= 1) { int y = __shfl_up_sync(~0u, ws, d); if (lane >= d) ws += y; }
        if (lane < 8) wsum[lane] = ws;
    }
    __syncthreads();
    int excl = (x - v) + (wid > 0 ? wsum[wid - 1] : 0);
    if (tid == 0) blockBase = atomicAdd(gTot, wsum[7]);
    __syncthreads();
    if (i < n) { int base = blockBase + excl; off[i] = base; cur[i] = base; }
}

__global__ void alloc_kernel(const int* cntP, int* offP, int* curP, int nP, int* totP,
                             const int* cntS, int* offS, int* curS, int nS, int* totS,
                             int BP) {
    if ((int)blockIdx.x < BP) alloc_seg(cntP, offP, curP, nP, totP, blockIdx.x);
    else                      alloc_seg(cntS, offS, curS, nS, totS, blockIdx.x - BP);
}

__global__ void fill_kernel(const int* __restrict__ es, const int* __restrict__ ep,
                            int* __restrict__ curS, int* __restrict__ curP,
                            int* __restrict__ adjS, int* __restrict__ adjP, int E) {
    int i = blockIdx.x * blockDim.x + threadIdx.x;
    if (i >= E) return;
    int s = es[i], p = ep[i];
    int ps = atomicAdd(&curS[s], 1); adjS[ps] = p;
    int pp = atomicAdd(&curP[p], 1); adjP[pp] = s;
}

// ======================= all conversions fused (fp32 -> fp16) ================
__global__ void convert_all(const float* __restrict__ pe, const int* __restrict__ pid, int NP,
                            __half* __restrict__ play16,
                            const float* __restrict__ song, int NS, __half* __restrict__ song16,
                            const float* Wl0, const float* Wr0, const float* Wl1, const float* Wr1,
                            const float* Wl2, const float* Wr2, const float* Wl3, const float* Wr3,
                            __half* __restrict__ W16, int Bg, int Bc) {
    int b = blockIdx.x;
    if (b < Bg) {
        int t = b * blockDim.x + threadIdx.x;
        int row = t >> 5, lane = t & 31;
        if (row >= NP) return;
        float4 v = __ldg((const float4*)(pe + (size_t)pid[row] * HF) + lane);
        ((uint2*)(play16 + (size_t)row * HF))[lane] = make_uint2(pack2h(v.x, v.y), pack2h(v.z, v.w));
    } else if (b < Bg + Bc) {
        int i = (b - Bg) * blockDim.x + threadIdx.x;
        if (i >= NS * HF / 4) return;
        float4 v = __ldg((const float4*)song + i);
        ((uint2*)song16)[i] = make_uint2(pack2h(v.x, v.y), pack2h(v.z, v.w));
    } else {
        int lb = b - Bg - Bc;                    // 0..511
        int pair = lb >> 7;
        int idx = (lb & 127) * 256 + threadIdx.x;
        const float* Wl = pair == 0 ? Wl0 : pair == 1 ? Wl1 : pair == 2 ? Wl2 : Wl3;
        const float* Wr = pair == 0 ? Wr0 : pair == 1 ? Wr1 : pair == 2 ? Wr2 : Wr3;
        int k = idx & 255, n = idx >> 8;
        float w = (k < 128) ? Wl[(size_t)k * HF + n] : Wr[(size_t)(k - 128) * HF + n];
        W16[(size_t)pair * HF * 256 + (size_t)n * 256 + k] = __float2half_rn(w);
    }
}

// ======================= fused CSR-mean-agg + fp16 dual GEMM =================
// out = act(mean_agg(src)[tile] @ Wl + b + A2 @ Wr).
// Phase 1: 8 warps aggregate 16 rows each, writing fp16 results directly into
//          the resident swizzled A1 SMEM region (2 chunks of 16KB).
// Phase 2: K-concat 256 in 4 chunks of 64; chunks 0-1 read A from the resident
//          region, chunks 2-3 stage A2; B staged every chunk.
#define FG_SMEM    65536
#define FG_A2STAGE 32768
#define FG_BSTAGE  49152

__device__ __forceinline__ int sw_off(int r, int q) {
    return r * 128 + ((q ^ (r & 7)) << 4);
}

__global__ __launch_bounds__(256, 2)
void fused_agg_gemm(const __half* __restrict__ src,      // gather source feature rows
                    const int* __restrict__ off, const int* __restrict__ cnt,
                    const int* __restrict__ adj,
                    const __half* __restrict__ A2, const __half* __restrict__ B16,
                    const float* __restrict__ bias,
                    float* __restrict__ outF, __half* __restrict__ out16,
                    int N, int doRelu) {
    extern __shared__ char smem[];
    const uint32_t sb = smem_u32(smem);
    const int tid = threadIdx.x, wid = tid >> 5, lane = tid & 31;
    const int rowBase = blockIdx.x * 128;

    // ---- phase 1: aggregate this tile's 128 rows into resident A1 smem ------
    // lane L owns features 4L..4L+3 (bytes 8L of the 256B row):
    //   chunk = L/16, quad = (L&15)/2, sub-8B = (L&1)*8  -> matches mainloop layout
    {
        const int chk = lane >> 4;
        const int qL  = (lane & 15) >> 1;
        const int sub = (lane & 1) << 3;
        for (int r16 = 0; r16 < 16; r16++) {
            int rl = wid * 16 + r16;
            int row = rowBase + rl;
            float4 acc = make_float4(0.f, 0.f, 0.f, 0.f);
            int c = 0;
            if (row < N) {
                int s0 = off[row]; c = cnt[row]; int s1 = s0 + c;
                for (int e = s0; e < s1; e += 32) {
                    int myE = e + lane;
                    int myIdx = (myE < s1) ? __ldg(adj + myE) : 0;
                    int n = min(32, s1 - e);
                    for (int j = 0; j < n; j++) {
                        int sidx = __shfl_sync(~0u, myIdx, j);
                        uint2 v = __ldg(((const uint2*)src) + (size_t)sidx * 32 + lane);
                        float2 f0 = __half22float2(*(const __half2*)&v.x);
                        float2 f1 = __half22float2(*(const __half2*)&v.y);
                        acc.x += f0.x; acc.y += f0.y; acc.z += f1.x; acc.w += f1.y;
                    }
                }
            }
            float w = 1.0f / (float)max(c, 1);
            uint2 pv = make_uint2(pack2h(acc.x * w, acc.y * w), pack2h(acc.z * w, acc.w * w));
            *(uint2*)(smem + chk * 16384 + sw_off(rl, qL) + sub) = pv;
        }
    }

    // ---- phase 2: GEMM mainloop ---------------------------------------------
    const int mBase = (wid & 3) * 32;
    const int nBase = (wid >> 2) * 64;

    float acc[2][8][4];
    #pragma unroll
    for (int mt = 0; mt < 2; mt++)
        #pragma unroll
        for (int nt = 0; nt < 8; nt++)
            #pragma unroll
            for (int j = 0; j < 4; j++) acc[mt][nt][j] = 0.f;

    const int rowA  = mBase + (lane & 15);
    const int partA = lane >> 4;
    const int swA   = rowA & 7;
    const int rowB  = nBase + ((lane >> 4) << 3) + (lane & 7);
    const int partB = (lane >> 3) & 1;
    const int swB   = rowB & 7;

    #pragma unroll 1
    for (int c = 0; c < 4; c++) {
        const int kA = (c & 1) * 64;
        const int kB = c * 64;

        __syncthreads();   // c=0: agg writes visible; c>0: stage buffers reusable
        #pragma unroll
        for (int u = 0; u < 4; u++) {
            int idx = tid + u * 256;          // 0..1023
            int r = idx >> 3, q = idx & 7;    // row 0..127, 16B quad 0..7
            int so = sw_off(r, q);
            if (c >= 2) {                     // stage A2 chunk
                int gr = rowBase + r;
                uint4 va = make_uint4(0, 0, 0, 0);
                if (gr < N) va = __ldg((const uint4*)(A2 + (size_t)gr * HF + kA) + q);
                *(uint4*)(smem + FG_A2STAGE + so) = va;
            }
            uint4 vb = __ldg((const uint4*)(B16 + (size_t)r * 256 + kB) + q);
            *(uint4*)(smem + FG_BSTAGE + so) = vb;
        }
        __syncthreads();

        const uint32_t aB = (c < 2) ? (sb + c * 16384) : (sb + FG_A2STAGE);
        const uint32_t bB = sb + FG_BSTAGE;

        #pragma unroll
        for (int ks = 0; ks < 4; ks++) {
            uint32_t a[2][4], b[8][2];
            const int qa = ((ks * 2 + partA) ^ swA) << 4;
            const int qb = ((ks * 2 + partB) ^ swB) << 4;
            #pragma unroll
            for (int mt = 0; mt < 2; mt++)
                ldsm_x4(a[mt], aB + (rowA + mt * 16) * 128 + qa);
            #pragma unroll
            for (int p = 0; p < 4; p++)
                ldsm_x4(&b[p * 2][0], bB + (rowB + p * 16) * 128 + qb);
            #pragma unroll
            for (int mt = 0; mt < 2; mt++)
                #pragma unroll
                for (int nt = 0; nt < 8; nt++)
                    mma_f16(acc[mt][nt], a[mt], b[nt]);
        }
    }

    // ---- epilogue: bias (+relu), nullable fp32 / fp16 stores ----------------
    const int erow = lane >> 2;
    const int ecol = (lane & 3) * 2;
    #pragma unroll
    for (int mt = 0; mt < 2; mt++) {
        #pragma unroll
        for (int nt = 0; nt < 8; nt++) {
            int col = nBase + nt * 8 + ecol;
            float2 bb = *(const float2*)(bias + col);
            #pragma unroll
            for (int h = 0; h < 2; h++) {
                int gr = rowBase + mBase + mt * 16 + erow + h * 8;
                if (gr < N) {
                    float x0 = acc[mt][nt][h * 2 + 0] + bb.x;
                    float x1 = acc[mt][nt][h * 2 + 1] + bb.y;
                    if (doRelu) { x0 = fmaxf(x0, 0.f); x1 = fmaxf(x1, 0.f); }
                    if (outF)
                        *(float2*)(outF + (size_t)gr * HF + col) = make_float2(x0, x1);
                    if (out16)
                        *(uint32_t*)(out16 + (size_t)gr * HF + col) = pack2h(x0, x1);
                }
            }
        }
    }
}

// ======================= launch (fork-join multi-stream graph) ===============
extern "C" void kernel_launch(void* const* d_in, const int* in_sizes, int n_in,
                              void* d_out, int out_size) {
    const float* song_x = (const float*)d_in[0];
    const int*   pid    = (const int*)  d_in[1];
    const int*   es     = (const int*)  d_in[2];
    const int*   ep     = (const int*)  d_in[3];
    const float* pemb   = (const float*)d_in[4];
    const float* Wl1_sp = (const float*)d_in[5];
    const float* Wr1_sp = (const float*)d_in[6];
    const float* b1_sp  = (const float*)d_in[7];
    const float* Wl1_ps = (const float*)d_in[8];
    const float* Wr1_ps = (const float*)d_in[9];
    const float* b1_ps  = (const float*)d_in[10];
    const float* Wl2_sp = (const float*)d_in[11];
    const float* Wr2_sp = (const float*)d_in[12];
    const float* b2_sp  = (const float*)d_in[13];
    const float* Wl2_ps = (const float*)d_in[14];
    const float* Wr2_ps = (const float*)d_in[15];
    const float* b2_ps  = (const float*)d_in[16];

    const int NS = in_sizes[0] / HF;
    const int NP = in_sizes[1];
    const int E  = in_sizes[2];

    int *cntP, *cntS, *offP, *offS, *curP, *curS, *adjP, *adjS, *totP, *totS;
    __half *song16, *play16, *p116, *s116, *W16;
    cudaGetSymbolAddress((void**)&cntP,  g_cntP);
    cudaGetSymbolAddress((void**)&cntS,  g_cntS);
    cudaGetSymbolAddress((void**)&offP,  g_offP);
    cudaGetSymbolAddress((void**)&offS,  g_offS);
    cudaGetSymbolAddress((void**)&curP,  g_curP);
    cudaGetSymbolAddress((void**)&curS,  g_curS);
    cudaGetSymbolAddress((void**)&adjP,  g_adjP);
    cudaGetSymbolAddress((void**)&adjS,  g_adjS);
    cudaGetSymbolAddress((void**)&totP,  g_totP);
    cudaGetSymbolAddress((void**)&totS,  g_totS);
    cudaGetSymbolAddress((void**)&song16, g_song16);
    cudaGetSymbolAddress((void**)&play16, g_play16);
    cudaGetSymbolAddress((void**)&p116,   g_p116);
    cudaGetSymbolAddress((void**)&s116,   g_s116);
    cudaGetSymbolAddress((void**)&W16,    g_W16);

    float* out_s2 = (float*)d_out;
    float* out_p2 = (float*)d_out + (size_t)NS * HF;

    // one-time resources (no device memory involved)
    static cudaStream_t strA = 0, strB = 0;
    static cudaEvent_t evStart = 0, evFill = 0, evConv = 0, evS1 = 0, evP1 = 0, evA = 0, evB = 0;
    if (!strA) {
        cudaFuncSetAttribute(fused_agg_gemm, cudaFuncAttributeMaxDynamicSharedMemorySize, FG_SMEM);
        cudaStreamCreateWithFlags(&strA, cudaStreamNonBlocking);
        cudaStreamCreateWithFlags(&strB, cudaStreamNonBlocking);
        cudaEventCreateWithFlags(&evStart, cudaEventDisableTiming);
        cudaEventCreateWithFlags(&evFill,  cudaEventDisableTiming);
        cudaEventCreateWithFlags(&evConv,  cudaEventDisableTiming);
        cudaEventCreateWithFlags(&evS1,    cudaEventDisableTiming);
        cudaEventCreateWithFlags(&evP1,    cudaEventDisableTiming);
        cudaEventCreateWithFlags(&evA,     cudaEventDisableTiming);
        cudaEventCreateWithFlags(&evB,     cudaEventDisableTiming);
    }

    const int tileP = (NP + 127) / 128;
    const int tileS = (NS + 127) / 128;
    const size_t WSZ = (size_t)HF * 256;

    // ---- fork: conversions on strB, CSR build on strA ----
    cudaEventRecord(evStart, 0);
    cudaStreamWaitEvent(strB, evStart, 0);
    cudaStreamWaitEvent(strA, evStart, 0);

    {   // strB: conversions (independent of CSR build)
        int Bg = (NP * 32 + 255) / 256;
        int Bc = (NS * HF / 4 + 255) / 256;
        convert_all<<<Bg + Bc + 512, 256, 0, strB>>>(pemb, pid, NP, play16,
                                                     song_x, NS, song16,
                                                     Wl1_sp, Wr1_sp, Wl1_ps, Wr1_ps,
                                                     Wl2_sp, Wr2_sp, Wl2_ps, Wr2_ps,
                                                     W16, Bg, Bc);
        cudaEventRecord(evConv, strB);
    }

    // strA: CSR build chain
    zero_cnt<<<(NS + 255) / 256, 256, 0, strA>>>(cntP, NP, cntS, NS, totP, totS);
    count_kernel<<<(E + 255) / 256, 256, 0, strA>>>(es, ep, cntS, cntP, E);
    {
        int BP = (NP + 255) / 256, BS = (NS + 255) / 256;
        alloc_kernel<<<BP + BS, 256, 0, strA>>>(cntP, offP, curP, NP, totP,
                                                cntS, offS, curS, NS, totS, BP);
    }
    fill_kernel<<<(E + 255) / 256, 256, 0, strA>>>(es, ep, curS, curP, adjS, adjP, E);
    cudaEventRecord(evFill, strA);

    // ---- layer 1: S-chain on strA, P-chain on strB ----
    // fusedS1: gathers play16 + dense song16 (evConv); CSR in-stream
    cudaStreamWaitEvent(strA, evConv, 0);
    fused_agg_gemm<<<tileS, 256, FG_SMEM, strA>>>(play16, offS, cntS, adjS,
                                                  song16, W16 + 1 * WSZ, b1_ps,
                                                  ((float*)0), s116, NS, 1);
    cudaEventRecord(evS1, strA);

    // fusedP1: gathers song16 + dense play16 (evConv in-stream); CSR (evFill)
    cudaStreamWaitEvent(strB, evFill, 0);
    fused_agg_gemm<<<tileP, 256, FG_SMEM, strB>>>(song16, offP, cntP, adjP,
                                                  play16, W16 + 0 * WSZ, b1_sp,
                                                  ((float*)0), p116, NP, 1);
    cudaEventRecord(evP1, strB);

    // ---- layer 2: crossed dependencies ----
    // fusedS2: gathers p116 (evP1); dense s116 (in-stream)
    cudaStreamWaitEvent(strA, evP1, 0);
    fused_agg_gemm<<<tileS, 256, FG_SMEM, strA>>>(p116, offS, cntS, adjS,
                                                  s116, W16 + 3 * WSZ, b2_ps,
                                                  out_s2, ((__half*)0), NS, 0);
    cudaEventRecord(evA, strA);

    // fusedP2: gathers s116 (evS1); dense p116 (in-stream)
    cudaStreamWaitEvent(strB, evS1, 0);
    fused_agg_gemm<<<tileP, 256, FG_SMEM, strB>>>(s116, offP, cntP, adjP,
                                                  p116, W16 + 2 * WSZ, b2_sp,
                                                  out_p2, ((__half*)0), NP, 0);
    cudaEventRecord(evB, strB);

    // ---- join back to the capture origin stream ----
    cudaStreamWaitEvent(0, evA, 0);
    cudaStreamWaitEvent(0, evB, 0);
}

// round 16
// speedup vs baseline: 1.6524x; 1.6524x over previous
#include <cuda_runtime.h>
#include <cuda_fp16.h>
#include <cstdint>

#define NS_MAX 100000
#define NP_MAX 20000
#define E_MAX  500000
#define HF 128

// ======================= device scratch (no allocation allowed) ==============
__device__ __half g_song16[NS_MAX * HF];
__device__ __half g_play16[NP_MAX * HF];
__device__ __half g_aggP16[NP_MAX * HF];
__device__ __half g_aggS16[NS_MAX * HF];
__device__ __half g_p116  [NP_MAX * HF];
__device__ __half g_s116  [NS_MAX * HF];
__device__ __half g_W16[4][HF * 256];   // B[n][k], k = concat(Wl,Wr), fp16

__device__ int g_cntP[NP_MAX], g_cntS[NS_MAX];
__device__ int g_offP[NP_MAX], g_offS[NS_MAX];
__device__ int g_curP[NP_MAX], g_curS[NS_MAX];
__device__ int g_adjP[E_MAX], g_adjS[E_MAX];
__device__ int g_totP, g_totS;

// ======================= helpers =============================================
__device__ __forceinline__ uint32_t smem_u32(const void* p) {
    uint32_t a;
    asm("{ .reg .u64 t; cvta.to.shared.u64 t, %1; cvt.u32.u64 %0, t; }" : "=r"(a) : "l"(p));
    return a;
}
__device__ __forceinline__ uint32_t pack2h(float a, float b) {
    __half2 h = __floats2half2_rn(a, b);
    return *(uint32_t*)&h;
}
__device__ __forceinline__ void ldsm_x4(uint32_t* r, uint32_t addr) {
    asm volatile("ldmatrix.sync.aligned.m8n8.x4.shared.b16 {%0,%1,%2,%3}, [%4];"
                 : "=r"(r[0]), "=r"(r[1]), "=r"(r[2]), "=r"(r[3]) : "r"(addr));
}
__device__ __forceinline__ void mma_f16(float* d, const uint32_t* a, const uint32_t* b) {
    asm volatile("mma.sync.aligned.m16n8k16.row.col.f32.f16.f16.f32 "
                 "{%0,%1,%2,%3}, {%4,%5,%6,%7}, {%8,%9}, {%0,%1,%2,%3};"
                 : "+f"(d[0]), "+f"(d[1]), "+f"(d[2]), "+f"(d[3])
                 : "r"(a[0]), "r"(a[1]), "r"(a[2]), "r"(a[3]), "r"(b[0]), "r"(b[1]));
}

// ======================= per-side CSR build ==================================
__global__ void zero_one(int* __restrict__ cnt, int n, int* __restrict__ tot) {
    int i = blockIdx.x * blockDim.x + threadIdx.x;
    if (i < n) cnt[i] = 0;
    if (i == 0) *tot = 0;
}

// histogram of dst[] into cnt[]
__global__ void count_one(const int* __restrict__ dst, int* __restrict__ cnt, int E) {
    int i = blockIdx.x * blockDim.x + threadIdx.x;
    if (i >= E) return;
    atomicAdd(&cnt[dst[i]], 1);
}

// parallel CSR allocation: block scan + one atomicAdd of block total.
__global__ void alloc_one(const int* __restrict__ cnt, int* __restrict__ off,
                          int* __restrict__ cur, int n, int* __restrict__ gTot) {
    __shared__ int wsum[8];
    __shared__ int blockBase;
    const int tid = threadIdx.x, lane = tid & 31, wid = tid >> 5;
    int i = blockIdx.x * 256 + tid;
    int v = (i < n) ? cnt[i] : 0;
    int x = v;
    #pragma unroll
    for (int d = 1; d < 32; d <<= 1) { int y = __shfl_up_sync(~0u, x, d); if (lane >= d) x += y; }
    if (lane == 31) wsum[wid] = x;
    __syncthreads();
    if (wid == 0) {
        int ws = (lane < 8) ? wsum[lane] : 0;
        #pragma unroll
        for (int d = 1; d < 8; d <<= 1) { int y = __shfl_up_sync(~0u, ws, d); if (lane >= d) ws += y; }
        if (lane < 8) wsum[lane] = ws;
    }
    __syncthreads();
    int excl = (x - v) + (wid > 0 ? wsum[wid - 1] : 0);
    if (tid == 0) blockBase = atomicAdd(gTot, wsum[7]);
    __syncthreads();
    if (i < n) { int base = blockBase + excl; off[i] = base; cur[i] = base; }
}

// fill adjacency for one side: adj[cur[dst]++] = other
__global__ void fill_one(const int* __restrict__ dst, const int* __restrict__ other,
                         int* __restrict__ cur, int* __restrict__ adj, int E) {
    int i = blockIdx.x * blockDim.x + threadIdx.x;
    if (i >= E) return;
    int d = dst[i];
    int pos = atomicAdd(&cur[d], 1);
    adj[pos] = other[i];
}

// ======================= all conversions fused (fp32 -> fp16) ================
__global__ void convert_all(const float* __restrict__ pe, const int* __restrict__ pid, int NP,
                            __half* __restrict__ play16,
                            const float* __restrict__ song, int NS, __half* __restrict__ song16,
                            const float* Wl0, const float* Wr0, const float* Wl1, const float* Wr1,
                            const float* Wl2, const float* Wr2, const float* Wl3, const float* Wr3,
                            __half* __restrict__ W16, int Bg, int Bc) {
    int b = blockIdx.x;
    if (b < Bg) {
        int t = b * blockDim.x + threadIdx.x;
        int row = t >> 5, lane = t & 31;
        if (row >= NP) return;
        float4 v = __ldg((const float4*)(pe + (size_t)pid[row] * HF) + lane);
        ((uint2*)(play16 + (size_t)row * HF))[lane] = make_uint2(pack2h(v.x, v.y), pack2h(v.z, v.w));
    } else if (b < Bg + Bc) {
        int i = (b - Bg) * blockDim.x + threadIdx.x;
        if (i >= NS * HF / 4) return;
        float4 v = __ldg((const float4*)song + i);
        ((uint2*)song16)[i] = make_uint2(pack2h(v.x, v.y), pack2h(v.z, v.w));
    } else {
        int lb = b - Bg - Bc;                    // 0..511
        int pair = lb >> 7;
        int idx = (lb & 127) * 256 + threadIdx.x;
        const float* Wl = pair == 0 ? Wl0 : pair == 1 ? Wl1 : pair == 2 ? Wl2 : Wl3;
        const float* Wr = pair == 0 ? Wr0 : pair == 1 ? Wr1 : pair == 2 ? Wr2 : Wr3;
        int k = idx & 255, n = idx >> 8;
        float w = (k < 128) ? Wl[(size_t)k * HF + n] : Wr[(size_t)(k - 128) * HF + n];
        W16[(size_t)pair * HF * 256 + (size_t)n * 256 + k] = __float2half_rn(w);
    }
}

// ======================= CSR mean-aggregation (fp16 gather, fp32 acc) ========
// One warp per dest row; gather loop unrolled x4 for MLP.
__global__ void csr_agg(const __half* __restrict__ src,
                        const int* __restrict__ off, const int* __restrict__ cnt,
                        const int* __restrict__ adj,
                        __half* __restrict__ out16, int Ndst) {
    int warp = (blockIdx.x * blockDim.x + threadIdx.x) >> 5;
    int lane = threadIdx.x & 31;
    if (warp >= Ndst) return;
    int s0 = off[warp];
    int c  = cnt[warp];
    int s1 = s0 + c;
    float4 acc = make_float4(0.f, 0.f, 0.f, 0.f);
    const uint2* s2 = (const uint2*)src;
    for (int e = s0; e < s1; e += 32) {
        int myE = e + lane;
        int myIdx = (myE < s1) ? __ldg(adj + myE) : 0;
        int n = min(32, s1 - e);
        int j = 0;
        for (; j + 4 <= n; j += 4) {
            int i0 = __shfl_sync(~0u, myIdx, j);
            int i1 = __shfl_sync(~0u, myIdx, j + 1);
            int i2 = __shfl_sync(~0u, myIdx, j + 2);
            int i3 = __shfl_sync(~0u, myIdx, j + 3);
            uint2 v0 = __ldg(s2 + (size_t)i0 * 32 + lane);
            uint2 v1 = __ldg(s2 + (size_t)i1 * 32 + lane);
            uint2 v2 = __ldg(s2 + (size_t)i2 * 32 + lane);
            uint2 v3 = __ldg(s2 + (size_t)i3 * 32 + lane);
            float2 a0 = __half22float2(*(const __half2*)&v0.x), b0 = __half22float2(*(const __half2*)&v0.y);
            float2 a1 = __half22float2(*(const __half2*)&v1.x), b1 = __half22float2(*(const __half2*)&v1.y);
            float2 a2 = __half22float2(*(const __half2*)&v2.x), b2 = __half22float2(*(const __half2*)&v2.y);
            float2 a3 = __half22float2(*(const __half2*)&v3.x), b3 = __half22float2(*(const __half2*)&v3.y);
            acc.x += (a0.x + a1.x) + (a2.x + a3.x);
            acc.y += (a0.y + a1.y) + (a2.y + a3.y);
            acc.z += (b0.x + b1.x) + (b2.x + b3.x);
            acc.w += (b0.y + b1.y) + (b2.y + b3.y);
        }
        for (; j < n; j++) {
            int sidx = __shfl_sync(~0u, myIdx, j);
            uint2 v = __ldg(s2 + (size_t)sidx * 32 + lane);
            float2 f0 = __half22float2(*(const __half2*)&v.x);
            float2 f1 = __half22float2(*(const __half2*)&v.y);
            acc.x += f0.x; acc.y += f0.y; acc.z += f1.x; acc.w += f1.y;
        }
    }
    float w = 1.0f / (float)max(c, 1);
    acc.x *= w; acc.y *= w; acc.z *= w; acc.w *= w;
    ((uint2*)(out16 + (size_t)warp * HF))[lane] = make_uint2(pack2h(acc.x, acc.y), pack2h(acc.z, acc.w));
}

// ======================= mma.sync fp16 single-pass dual GEMM =================
#define GEMM_SMEM 32768
#define OFF_A 0
#define OFF_B 16384

__device__ __forceinline__ int sw_off(int r, int q) {
    return r * 128 + ((q ^ (r & 7)) << 4);
}

__global__ __launch_bounds__(256, 2)
void mma_dual_gemm(const __half* __restrict__ A1, const __half* __restrict__ A2,
                   const __half* __restrict__ B16,
                   const float* __restrict__ bias,
                   float* __restrict__ outF, __half* __restrict__ out16,
                   int N, int doRelu) {
    extern __shared__ char smem[];
    const uint32_t sb = smem_u32(smem);
    const int tid = threadIdx.x, wid = tid >> 5, lane = tid & 31;
    const int rowBase = blockIdx.x * 128;

    const int mBase = (wid & 3) * 32;
    const int nBase = (wid >> 2) * 64;

    float acc[2][8][4];
    #pragma unroll
    for (int mt = 0; mt < 2; mt++)
        #pragma unroll
        for (int nt = 0; nt < 8; nt++)
            #pragma unroll
            for (int j = 0; j < 4; j++) acc[mt][nt][j] = 0.f;

    const int rowA  = mBase + (lane & 15);
    const int partA = lane >> 4;
    const int swA   = rowA & 7;
    const int rowB  = nBase + ((lane >> 4) << 3) + (lane & 7);
    const int partB = (lane >> 3) & 1;
    const int swB   = rowB & 7;

    #pragma unroll 1
    for (int c = 0; c < 4; c++) {
        const __half* A = (c < 2) ? A1 : A2;
        const int kA = (c & 1) * 64;
        const int kB = c * 64;

        __syncthreads();   // previous chunk's compute done -> smem reusable
        #pragma unroll
        for (int u = 0; u < 4; u++) {
            int idx = tid + u * 256;          // 0..1023
            int r = idx >> 3, q = idx & 7;    // row 0..127, 16B quad 0..7
            int gr = rowBase + r;
            uint4 va = make_uint4(0, 0, 0, 0);
            if (gr < N) va = __ldg((const uint4*)(A + (size_t)gr * HF + kA) + q);
            uint4 vb = __ldg((const uint4*)(B16 + (size_t)r * 256 + kB) + q);
            int so = sw_off(r, q);
            *(uint4*)(smem + OFF_A + so) = va;
            *(uint4*)(smem + OFF_B + so) = vb;
        }
        __syncthreads();

        #pragma unroll
        for (int ks = 0; ks < 4; ks++) {
            uint32_t a[2][4], b[8][2];
            const int qa = ((ks * 2 + partA) ^ swA) << 4;
            const int qb = ((ks * 2 + partB) ^ swB) << 4;
            #pragma unroll
            for (int mt = 0; mt < 2; mt++)
                ldsm_x4(a[mt], sb + OFF_A + (rowA + mt * 16) * 128 + qa);
            #pragma unroll
            for (int p = 0; p < 4; p++)
                ldsm_x4(&b[p * 2][0], sb + OFF_B + (rowB + p * 16) * 128 + qb);
            #pragma unroll
            for (int mt = 0; mt < 2; mt++)
                #pragma unroll
                for (int nt = 0; nt < 8; nt++)
                    mma_f16(acc[mt][nt], a[mt], b[nt]);
        }
    }

    // ---- epilogue: bias (+relu), nullable fp32 / fp16 stores ----------------
    const int erow = lane >> 2;
    const int ecol = (lane & 3) * 2;
    #pragma unroll
    for (int mt = 0; mt < 2; mt++) {
        #pragma unroll
        for (int nt = 0; nt < 8; nt++) {
            int col = nBase + nt * 8 + ecol;
            float2 bb = *(const float2*)(bias + col);
            #pragma unroll
            for (int h = 0; h < 2; h++) {
                int gr = rowBase + mBase + mt * 16 + erow + h * 8;
                if (gr < N) {
                    float x0 = acc[mt][nt][h * 2 + 0] + bb.x;
                    float x1 = acc[mt][nt][h * 2 + 1] + bb.y;
                    if (doRelu) { x0 = fmaxf(x0, 0.f); x1 = fmaxf(x1, 0.f); }
                    if (outF)
                        *(float2*)(outF + (size_t)gr * HF + col) = make_float2(x0, x1);
                    if (out16)
                        *(uint32_t*)(out16 + (size_t)gr * HF + col) = pack2h(x0, x1);
                }
            }
        }
    }
}

// ======================= launch (fork-join multi-stream graph) ===============
extern "C" void kernel_launch(void* const* d_in, const int* in_sizes, int n_in,
                              void* d_out, int out_size) {
    const float* song_x = (const float*)d_in[0];
    const int*   pid    = (const int*)  d_in[1];
    const int*   es     = (const int*)  d_in[2];
    const int*   ep     = (const int*)  d_in[3];
    const float* pemb   = (const float*)d_in[4];
    const float* Wl1_sp = (const float*)d_in[5];
    const float* Wr1_sp = (const float*)d_in[6];
    const float* b1_sp  = (const float*)d_in[7];
    const float* Wl1_ps = (const float*)d_in[8];
    const float* Wr1_ps = (const float*)d_in[9];
    const float* b1_ps  = (const float*)d_in[10];
    const float* Wl2_sp = (const float*)d_in[11];
    const float* Wr2_sp = (const float*)d_in[12];
    const float* b2_sp  = (const float*)d_in[13];
    const float* Wl2_ps = (const float*)d_in[14];
    const float* Wr2_ps = (const float*)d_in[15];
    const float* b2_ps  = (const float*)d_in[16];

    const int NS = in_sizes[0] / HF;
    const int NP = in_sizes[1];
    const int E  = in_sizes[2];

    int *cntP, *cntS, *offP, *offS, *curP, *curS, *adjP, *adjS, *totP, *totS;
    __half *song16, *play16, *aggP16, *aggS16, *p116, *s116, *W16;
    cudaGetSymbolAddress((void**)&cntP,  g_cntP);
    cudaGetSymbolAddress((void**)&cntS,  g_cntS);
    cudaGetSymbolAddress((void**)&offP,  g_offP);
    cudaGetSymbolAddress((void**)&offS,  g_offS);
    cudaGetSymbolAddress((void**)&curP,  g_curP);
    cudaGetSymbolAddress((void**)&curS,  g_curS);
    cudaGetSymbolAddress((void**)&adjP,  g_adjP);
    cudaGetSymbolAddress((void**)&adjS,  g_adjS);
    cudaGetSymbolAddress((void**)&totP,  g_totP);
    cudaGetSymbolAddress((void**)&totS,  g_totS);
    cudaGetSymbolAddress((void**)&song16, g_song16);
    cudaGetSymbolAddress((void**)&play16, g_play16);
    cudaGetSymbolAddress((void**)&aggP16, g_aggP16);
    cudaGetSymbolAddress((void**)&aggS16, g_aggS16);
    cudaGetSymbolAddress((void**)&p116,   g_p116);
    cudaGetSymbolAddress((void**)&s116,   g_s116);
    cudaGetSymbolAddress((void**)&W16,    g_W16);

    float* out_s2 = (float*)d_out;
    float* out_p2 = (float*)d_out + (size_t)NS * HF;

    // one-time resources (no device memory involved)
    static cudaStream_t strA = 0, strB = 0;
    static cudaEvent_t evStart = 0, evConv = 0, evS1 = 0, evP1 = 0, evA = 0, evB = 0;
    if (!strA) {
        cudaFuncSetAttribute(mma_dual_gemm, cudaFuncAttributeMaxDynamicSharedMemorySize, GEMM_SMEM);
        cudaStreamCreateWithFlags(&strA, cudaStreamNonBlocking);
        cudaStreamCreateWithFlags(&strB, cudaStreamNonBlocking);
        cudaEventCreateWithFlags(&evStart, cudaEventDisableTiming);
        cudaEventCreateWithFlags(&evConv,  cudaEventDisableTiming);
        cudaEventCreateWithFlags(&evS1,    cudaEventDisableTiming);
        cudaEventCreateWithFlags(&evP1,    cudaEventDisableTiming);
        cudaEventCreateWithFlags(&evA,     cudaEventDisableTiming);
        cudaEventCreateWithFlags(&evB,     cudaEventDisableTiming);
    }

    const int aggBlkP = (NP + 7) / 8;
    const int aggBlkS = (NS + 7) / 8;
    const int tileP = (NP + 127) / 128;
    const int tileS = (NS + 127) / 128;
    const size_t WSZ = (size_t)HF * 256;

    // ---- fork ----
    cudaEventRecord(evStart, 0);
    cudaStreamWaitEvent(strB, evStart, 0);
    cudaStreamWaitEvent(strA, evStart, 0);

    // strB: conversions, then P-side CSR build (both feed the P-chain)
    {
        int Bg = (NP * 32 + 255) / 256;
        int Bc = (NS * HF / 4 + 255) / 256;
        convert_all<<<Bg + Bc + 512, 256, 0, strB>>>(pemb, pid, NP, play16,
                                                     song_x, NS, song16,
                                                     Wl1_sp, Wr1_sp, Wl1_ps, Wr1_ps,
                                                     Wl2_sp, Wr2_sp, Wl2_ps, Wr2_ps,
                                                     W16, Bg, Bc);
        cudaEventRecord(evConv, strB);
    }
    zero_one<<<(NP + 255) / 256, 256, 0, strB>>>(cntP, NP, totP);
    count_one<<<(E + 255) / 256, 256, 0, strB>>>(ep, cntP, E);
    alloc_one<<<(NP + 255) / 256, 256, 0, strB>>>(cntP, offP, curP, NP, totP);
    fill_one<<<(E + 255) / 256, 256, 0, strB>>>(ep, es, curP, adjP, E);

    // strA: S-side CSR build (runs concurrently with convert + P-build)
    zero_one<<<(NS + 255) / 256, 256, 0, strA>>>(cntS, NS, totS);
    count_one<<<(E + 255) / 256, 256, 0, strA>>>(es, cntS, E);
    alloc_one<<<(NS + 255) / 256, 256, 0, strA>>>(cntS, offS, curS, NS, totS);
    fill_one<<<(E + 255) / 256, 256, 0, strA>>>(es, ep, curS, adjS, E);

    // ---- layer 1: S-chain on strA, P-chain on strB ----
    // aggS gathers play16 (needs evConv); S-CSR in-stream
    cudaStreamWaitEvent(strA, evConv, 0);
    csr_agg<<<aggBlkS, 256, 0, strA>>>(play16, offS, cntS, adjS, aggS16, NS);
    mma_dual_gemm<<<tileS, 256, GEMM_SMEM, strA>>>(aggS16, song16, W16 + 1 * WSZ, b1_ps,
                                                   ((float*)0), s116, NS, 1);
    cudaEventRecord(evS1, strA);

    // aggP gathers song16 (evConv in-stream) with P-CSR in-stream
    csr_agg<<<aggBlkP, 256, 0, strB>>>(song16, offP, cntP, adjP, aggP16, NP);
    mma_dual_gemm<<<tileP, 256, GEMM_SMEM, strB>>>(aggP16, play16, W16 + 0 * WSZ, b1_sp,
                                                   ((float*)0), p116, NP, 1);
    cudaEventRecord(evP1, strB);

    // ---- layer 2: crossed dependencies ----
    // S-side layer 2 gathers p116 (evP1); dense s116 (in-stream)
    cudaStreamWaitEvent(strA, evP1, 0);
    csr_agg<<<aggBlkS, 256, 0, strA>>>(p116, offS, cntS, adjS, aggS16, NS);
    mma_dual_gemm<<<tileS, 256, GEMM_SMEM, strA>>>(aggS16, s116, W16 + 3 * WSZ, b2_ps,
                                                   out_s2, ((__half*)0), NS, 0);
    cudaEventRecord(evA, strA);

    // P-side layer 2 gathers s116 (evS1); dense p116 (in-stream)
    cudaStreamWaitEvent(strB, evS1, 0);
    csr_agg<<<aggBlkP, 256, 0, strB>>>(s116, offP, cntP, adjP, aggP16, NP);
    mma_dual_gemm<<<tileP, 256, GEMM_SMEM, strB>>>(aggP16, p116, W16 + 2 * WSZ, b2_sp,
                                                   out_p2, ((__half*)0), NP, 0);
    cudaEventRecord(evB, strB);

    // ---- join back to the capture origin stream ----
    cudaStreamWaitEvent(0, evA, 0);
    cudaStreamWaitEvent(0, evB, 0);
}